// round 4
// baseline (speedup 1.0000x reference)
#include <cuda_runtime.h>

// Problem constants
#define T_STEPS 4
#define BATCH   32
#define CH      384
#define HW      196
#define HEADS   8
#define DH      48
#define CHW     (CH*HW)          // 75264
#define BCHW    (BATCH*CHW)      // 2408448
#define TOTAL   (T_STEPS*BCHW)   // 9633792
#define NTOT    (T_STEPS*BATCH*HW) // 25088  (= 98 * 256 exactly)
#define NCHUNK  (CH/8)           // 48 k-chunks

// Scratch (static device globals -- allocation-guard safe)
__device__ float g_qbn[TOTAL];
__device__ float g_kbn[TOTAL];
__device__ float g_y[TOTAL];
__device__ float g_zbn[TOTAL];

// ---------------------------------------------------------------------------
// SGEMM 128(M) x 256(N) x 8(K-chunk), 256 threads, 8x16 microtile, fused BN.
// Microtile slots: m in {ty*4+i, 64+ty*4+i}, n in {g*64 + tx*4 + j, g=0..3}.
// 96 B LDS per 128 FMAs per thread per k-step -> FMA-bound, not crossbar-bound.
// Double-buffered smem, one __syncthreads per chunk, static buffer parity.
// ---------------------------------------------------------------------------
__device__ __forceinline__ void gemm_bn_body(
    const float* __restrict__ X, const float* __restrict__ W,
    const float* __restrict__ gamma, const float* __restrict__ beta,
    const float* __restrict__ mean,  const float* __restrict__ var,
    const float* __restrict__ bias,  float* __restrict__ out)
{
    __shared__ float As[2][8][128];   // [stage][k][m]
    __shared__ float Bs[2][8][256];   // [stage][k][n]
    __shared__ int   colOff[256];

    const int tid   = threadIdx.x;
    const int mbase = blockIdx.y * 128;
    const int nbase = blockIdx.x * 256;

    {
        int n  = nbase + tid;
        int tb = n / HW;
        colOff[tid] = tb * CHW + (n - tb * HW);
    }
    __syncthreads();

    const int tx = tid & 15;     // n direction (16)
    const int ty = tid >> 4;     // m direction (16)

    // load mapping
    const int a_row = tid >> 1;        // 0..127
    const int a_col = (tid & 1) * 4;   // 0 or 4
    const int b_k   = tid >> 5;        // 0..7
    const int b_n   = (tid & 31) * 4;  // 0..124 (half 0); +128 for half 1

    int bo[8];
#pragma unroll
    for (int h = 0; h < 2; h++)
#pragma unroll
        for (int j = 0; j < 4; j++)
            bo[h * 4 + j] = colOff[h * 128 + b_n + j];

    const float* wptr = &W[(mbase + a_row) * CH + a_col];

    float acc[8][16];
#pragma unroll
    for (int i = 0; i < 8; i++)
#pragma unroll
        for (int j = 0; j < 16; j++) acc[i][j] = 0.f;

    // --- preload chunk 0 into stage 0 ---
    {
        float4 av = *reinterpret_cast<const float4*>(wptr);
        const int krow = b_k * HW;
        As[0][a_col + 0][a_row] = av.x;
        As[0][a_col + 1][a_row] = av.y;
        As[0][a_col + 2][a_row] = av.z;
        As[0][a_col + 3][a_row] = av.w;
        *reinterpret_cast<float4*>(&Bs[0][b_k][b_n]) =
            make_float4(X[bo[0] + krow], X[bo[1] + krow], X[bo[2] + krow], X[bo[3] + krow]);
        *reinterpret_cast<float4*>(&Bs[0][b_k][128 + b_n]) =
            make_float4(X[bo[4] + krow], X[bo[5] + krow], X[bo[6] + krow], X[bo[7] + krow]);
    }
    __syncthreads();

#define COMPUTE_STAGE(S)                                                        \
    _Pragma("unroll")                                                           \
    for (int k = 0; k < 8; k++) {                                               \
        float4 A0 = *reinterpret_cast<const float4*>(&As[S][k][ty * 4]);        \
        float4 A1 = *reinterpret_cast<const float4*>(&As[S][k][64 + ty * 4]);   \
        float4 B0 = *reinterpret_cast<const float4*>(&Bs[S][k][tx * 4]);        \
        float4 B1 = *reinterpret_cast<const float4*>(&Bs[S][k][64 + tx * 4]);   \
        float4 B2 = *reinterpret_cast<const float4*>(&Bs[S][k][128 + tx * 4]);  \
        float4 B3 = *reinterpret_cast<const float4*>(&Bs[S][k][192 + tx * 4]);  \
        float ar[8]  = {A0.x, A0.y, A0.z, A0.w, A1.x, A1.y, A1.z, A1.w};        \
        float br[16] = {B0.x, B0.y, B0.z, B0.w, B1.x, B1.y, B1.z, B1.w,         \
                        B2.x, B2.y, B2.z, B2.w, B3.x, B3.y, B3.z, B3.w};        \
        _Pragma("unroll")                                                       \
        for (int i = 0; i < 8; i++)                                             \
            _Pragma("unroll")                                                   \
            for (int j = 0; j < 16; j++)                                        \
                acc[i][j] = fmaf(ar[i], br[j], acc[i][j]);                      \
    }

#pragma unroll 1
    for (int it = 0; it < NCHUNK; it += 2) {
        // -- stage 0 compute, prefetch chunk it+1 -> stage 1 (always valid) --
        {
            float4 av = *reinterpret_cast<const float4*>(wptr + (it + 1) * 8);
            const int krow = ((it + 1) * 8 + b_k) * HW;
            float x0 = X[bo[0] + krow], x1 = X[bo[1] + krow];
            float x2 = X[bo[2] + krow], x3 = X[bo[3] + krow];
            float x4 = X[bo[4] + krow], x5 = X[bo[5] + krow];
            float x6 = X[bo[6] + krow], x7 = X[bo[7] + krow];

            COMPUTE_STAGE(0)

            As[1][a_col + 0][a_row] = av.x;
            As[1][a_col + 1][a_row] = av.y;
            As[1][a_col + 2][a_row] = av.z;
            As[1][a_col + 3][a_row] = av.w;
            *reinterpret_cast<float4*>(&Bs[1][b_k][b_n])       = make_float4(x0, x1, x2, x3);
            *reinterpret_cast<float4*>(&Bs[1][b_k][128 + b_n]) = make_float4(x4, x5, x6, x7);
            __syncthreads();
        }
        // -- stage 1 compute, prefetch chunk it+2 -> stage 0 (except last) --
        if (it + 2 < NCHUNK) {
            float4 av = *reinterpret_cast<const float4*>(wptr + (it + 2) * 8);
            const int krow = ((it + 2) * 8 + b_k) * HW;
            float x0 = X[bo[0] + krow], x1 = X[bo[1] + krow];
            float x2 = X[bo[2] + krow], x3 = X[bo[3] + krow];
            float x4 = X[bo[4] + krow], x5 = X[bo[5] + krow];
            float x6 = X[bo[6] + krow], x7 = X[bo[7] + krow];

            COMPUTE_STAGE(1)

            As[0][a_col + 0][a_row] = av.x;
            As[0][a_col + 1][a_row] = av.y;
            As[0][a_col + 2][a_row] = av.z;
            As[0][a_col + 3][a_row] = av.w;
            *reinterpret_cast<float4*>(&Bs[0][b_k][b_n])       = make_float4(x0, x1, x2, x3);
            *reinterpret_cast<float4*>(&Bs[0][b_k][128 + b_n]) = make_float4(x4, x5, x6, x7);
            __syncthreads();
        } else {
            COMPUTE_STAGE(1)
        }
    }
#undef COMPUTE_STAGE

    // BN (+optional conv bias) epilogue, matching reference op order exactly
#pragma unroll
    for (int i = 0; i < 8; i++) {
        int m = (i < 4) ? (ty * 4 + i) : (64 + ty * 4 + (i - 4));
        int o = mbase + m;
        float inv = gamma[o] / sqrtf(var[o] + 1e-5f);
        float sh  = beta[o] - mean[o] * inv;
        float bv  = bias ? bias[o] : 0.f;
        float* orow = out + o * HW;
#pragma unroll
        for (int j = 0; j < 16; j++) {
            int n = (j >> 2) * 64 + tx * 4 + (j & 3);
            float v = acc[i][j] + bv;
            orow[colOff[n]] = v * inv + sh;
        }
    }
}

__global__ void __launch_bounds__(256, 1) gemm_q_kernel(
    const float* __restrict__ X, const float* __restrict__ W,
    const float* __restrict__ g, const float* __restrict__ b,
    const float* __restrict__ m, const float* __restrict__ v)
{
    gemm_bn_body(X, W, g, b, m, v, nullptr, g_qbn);
}

__global__ void __launch_bounds__(256, 1) gemm_k_kernel(
    const float* __restrict__ X, const float* __restrict__ W,
    const float* __restrict__ g, const float* __restrict__ b,
    const float* __restrict__ m, const float* __restrict__ v)
{
    gemm_bn_body(X, W, g, b, m, v, nullptr, g_kbn);
}

__global__ void __launch_bounds__(256, 1) gemm_proj_kernel(
    const float* __restrict__ W,
    const float* __restrict__ g, const float* __restrict__ b,
    const float* __restrict__ m, const float* __restrict__ v,
    const float* __restrict__ bias)
{
    gemm_bn_body(g_y, W, g, b, m, v, bias, g_zbn);
}

// ---------------------------------------------------------------------------
// LIF on q and k (per channel, over T), per-head sum-pool, attn LIF (vth=0.5),
// gate k spikes -> binary y.  One CTA per (b, head); one thread per hw.
// ---------------------------------------------------------------------------
__global__ void lif_attn_kernel()
{
    int bh   = blockIdx.x;
    int b    = bh >> 3;
    int head = bh & 7;
    int hw   = threadIdx.x;
    if (hw >= HW) return;

    int cbase = head * DH;
    int base0 = b * CHW + cbase * HW + hw;

    float qs[4] = {0.f, 0.f, 0.f, 0.f};
    unsigned long long kb[4] = {0ull, 0ull, 0ull, 0ull};

    for (int d = 0; d < DH; d++) {
        int idx = base0 + d * HW;
        float vq = 0.f, vk = 0.f;
#pragma unroll
        for (int t = 0; t < 4; t++) {
            float xq = g_qbn[idx + t * BCHW];
            float xk = g_kbn[idx + t * BCHW];
            float hq = vq + (xq - vq) * 0.5f;   // tau = 2
            float hk = vk + (xk - vk) * 0.5f;
            bool sq = (hq - 1.0f) >= 0.0f;      // v_th = 1
            bool sk = (hk - 1.0f) >= 0.0f;
            vq = sq ? 0.f : hq;                 // hard reset
            vk = sk ? 0.f : hk;
            if (sq) qs[t] += 1.0f;
            if (sk) kb[t] |= (1ull << d);
        }
    }

    // attention LIF over the per-head spike-count (exact small integers)
    float va = 0.f;
#pragma unroll
    for (int t = 0; t < 4; t++) {
        float h = va + (qs[t] - va) * 0.5f;
        bool s  = (h - 0.5f) >= 0.0f;           // v_th = 0.5
        va = s ? 0.f : h;
        unsigned long long kbt = s ? kb[t] : 0ull;
        int ob = t * BCHW + base0;
        for (int d = 0; d < DH; d++)
            g_y[ob + d * HW] = ((kbt >> d) & 1ull) ? 1.0f : 0.0f;
    }
}

// ---------------------------------------------------------------------------
// Final LIF on the projected/BN'd activations -> output spikes
// ---------------------------------------------------------------------------
__global__ void lif_out_kernel(float* __restrict__ out)
{
    int idx = blockIdx.x * blockDim.x + threadIdx.x;
    if (idx >= BCHW) return;
    float v = 0.f;
#pragma unroll
    for (int t = 0; t < 4; t++) {
        float x = g_zbn[idx + t * BCHW];
        float h = v + (x - v) * 0.5f;
        bool s  = (h - 1.0f) >= 0.0f;
        v = s ? 0.f : h;
        out[idx + t * BCHW] = s ? 1.0f : 0.0f;
    }
}

// ---------------------------------------------------------------------------
extern "C" void kernel_launch(void* const* d_in, const int* in_sizes, int n_in,
                              void* d_out, int out_size)
{
    const float* x          = (const float*)d_in[0];
    const float* q_w        = (const float*)d_in[1];
    const float* q_gamma    = (const float*)d_in[2];
    const float* q_beta     = (const float*)d_in[3];
    const float* q_mean     = (const float*)d_in[4];
    const float* q_var      = (const float*)d_in[5];
    const float* k_w        = (const float*)d_in[6];
    const float* k_gamma    = (const float*)d_in[7];
    const float* k_beta     = (const float*)d_in[8];
    const float* k_mean     = (const float*)d_in[9];
    const float* k_var      = (const float*)d_in[10];
    const float* proj_w     = (const float*)d_in[11];
    const float* proj_b     = (const float*)d_in[12];
    const float* proj_gamma = (const float*)d_in[13];
    const float* proj_beta  = (const float*)d_in[14];
    const float* proj_mean  = (const float*)d_in[15];
    const float* proj_var   = (const float*)d_in[16];

    dim3 ggrid(NTOT / 256, CH / 128);   // (98, 3)

    gemm_q_kernel<<<ggrid, 256>>>(x, q_w, q_gamma, q_beta, q_mean, q_var);
    gemm_k_kernel<<<ggrid, 256>>>(x, k_w, k_gamma, k_beta, k_mean, k_var);
    lif_attn_kernel<<<BATCH * HEADS, 224>>>();
    gemm_proj_kernel<<<ggrid, 256>>>(proj_w, proj_gamma, proj_beta,
                                     proj_mean, proj_var, proj_b);
    lif_out_kernel<<<(BCHW + 255) / 256, 256>>>((float*)d_out);
}

// round 7
// speedup vs baseline: 1.0585x; 1.0585x over previous
#include <cuda_runtime.h>
#include <cuda_bf16.h>
#include <cstdint>

// Problem constants
#define T_STEPS 4
#define BATCH   32
#define CH      384
#define HW      196
#define HEADS   8
#define DH      48
#define CHW     (CH*HW)          // 75264
#define BCHW    (BATCH*CHW)      // 2408448
#define TOTAL   (T_STEPS*BCHW)   // 9633792
#define NTOT    (T_STEPS*BATCH*HW) // 25088  (= 196 * 128 exactly)
#define NCHUNK  (CH/8)           // 48 k-chunks (fp32 SGEMM)

// Scratch (static device globals -- allocation-guard safe)
__device__ float g_qbn[TOTAL];
__device__ float g_kbn[TOTAL];
__device__ float g_zbn[TOTAL];
__device__ __nv_bfloat16 g_ybf[TOTAL];   // proj input, [n][c] row-major, exact 0/1
__device__ __nv_bfloat16 g_w0[CH*CH];    // proj_w 3-way exact bf16 split
__device__ __nv_bfloat16 g_w1[CH*CH];
__device__ __nv_bfloat16 g_w2[CH*CH];

// ===========================================================================
// Q/K SGEMM (R2 config: 128x128 tile, 8x8 microtile, 2 CTAs/SM, double-buffer)
// ===========================================================================
__device__ __forceinline__ void gemm_bn_body(
    const float* __restrict__ X, const float* __restrict__ W,
    const float* __restrict__ gamma, const float* __restrict__ beta,
    const float* __restrict__ mean,  const float* __restrict__ var,
    float* __restrict__ out)
{
    __shared__ float As[2][8][128];
    __shared__ float Bs[2][8][128];
    __shared__ int   colOff[128];

    const int tid   = threadIdx.x;
    const int mbase = blockIdx.y * 128;
    const int nbase = blockIdx.x * 128;

    if (tid < 128) {
        int n  = nbase + tid;
        int tb = n / HW;
        colOff[tid] = tb * CHW + (n - tb * HW);
    }
    __syncthreads();

    const int tx = tid & 15;
    const int ty = tid >> 4;

    const int a_row = tid >> 1;
    const int a_col = (tid & 1) * 4;
    const int b_k   = tid >> 5;
    const int b_n   = (tid & 31) * 4;

    const int bo0 = colOff[b_n + 0];
    const int bo1 = colOff[b_n + 1];
    const int bo2 = colOff[b_n + 2];
    const int bo3 = colOff[b_n + 3];

    const float* wptr = &W[(mbase + a_row) * CH + a_col];

    float acc[8][8];
#pragma unroll
    for (int i = 0; i < 8; i++)
#pragma unroll
        for (int j = 0; j < 8; j++) acc[i][j] = 0.f;

    {
        float4 av = *reinterpret_cast<const float4*>(wptr);
        const int krow = b_k * HW;
        As[0][a_col + 0][a_row] = av.x;
        As[0][a_col + 1][a_row] = av.y;
        As[0][a_col + 2][a_row] = av.z;
        As[0][a_col + 3][a_row] = av.w;
        *reinterpret_cast<float4*>(&Bs[0][b_k][b_n]) =
            make_float4(X[bo0 + krow], X[bo1 + krow], X[bo2 + krow], X[bo3 + krow]);
    }
    __syncthreads();

#define COMPUTE_STAGE(S)                                                        \
    _Pragma("unroll")                                                           \
    for (int k = 0; k < 8; k++) {                                               \
        float4 A0 = *reinterpret_cast<const float4*>(&As[S][k][ty * 4]);        \
        float4 A1 = *reinterpret_cast<const float4*>(&As[S][k][64 + ty * 4]);   \
        float4 B0 = *reinterpret_cast<const float4*>(&Bs[S][k][tx * 4]);        \
        float4 B1 = *reinterpret_cast<const float4*>(&Bs[S][k][64 + tx * 4]);   \
        float ar[8] = {A0.x, A0.y, A0.z, A0.w, A1.x, A1.y, A1.z, A1.w};         \
        float br[8] = {B0.x, B0.y, B0.z, B0.w, B1.x, B1.y, B1.z, B1.w};         \
        _Pragma("unroll")                                                       \
        for (int i = 0; i < 8; i++)                                             \
            _Pragma("unroll")                                                   \
            for (int j = 0; j < 8; j++)                                         \
                acc[i][j] = fmaf(ar[i], br[j], acc[i][j]);                      \
    }

#pragma unroll 1
    for (int it = 0; it < NCHUNK; it += 2) {
        {
            float4 av = *reinterpret_cast<const float4*>(wptr + (it + 1) * 8);
            const int krow = ((it + 1) * 8 + b_k) * HW;
            float x0 = X[bo0 + krow], x1 = X[bo1 + krow];
            float x2 = X[bo2 + krow], x3 = X[bo3 + krow];

            COMPUTE_STAGE(0)

            As[1][a_col + 0][a_row] = av.x;
            As[1][a_col + 1][a_row] = av.y;
            As[1][a_col + 2][a_row] = av.z;
            As[1][a_col + 3][a_row] = av.w;
            *reinterpret_cast<float4*>(&Bs[1][b_k][b_n]) = make_float4(x0, x1, x2, x3);
            __syncthreads();
        }
        if (it + 2 < NCHUNK) {
            float4 av = *reinterpret_cast<const float4*>(wptr + (it + 2) * 8);
            const int krow = ((it + 2) * 8 + b_k) * HW;
            float x0 = X[bo0 + krow], x1 = X[bo1 + krow];
            float x2 = X[bo2 + krow], x3 = X[bo3 + krow];

            COMPUTE_STAGE(1)

            As[0][a_col + 0][a_row] = av.x;
            As[0][a_col + 1][a_row] = av.y;
            As[0][a_col + 2][a_row] = av.z;
            As[0][a_col + 3][a_row] = av.w;
            *reinterpret_cast<float4*>(&Bs[0][b_k][b_n]) = make_float4(x0, x1, x2, x3);
            __syncthreads();
        } else {
            COMPUTE_STAGE(1)
        }
    }
#undef COMPUTE_STAGE

#pragma unroll
    for (int i = 0; i < 8; i++) {
        int m = (i < 4) ? (ty * 4 + i) : (64 + ty * 4 + (i - 4));
        int o = mbase + m;
        float inv = gamma[o] / sqrtf(var[o] + 1e-5f);
        float sh  = beta[o] - mean[o] * inv;
#pragma unroll
        for (int j = 0; j < 8; j++) {
            int n = (j < 4) ? (tx * 4 + j) : (64 + tx * 4 + (j - 4));
            out[colOff[n] + o * HW] = acc[i][j] * inv + sh;
        }
    }
}

__global__ void __launch_bounds__(256, 2) gemm_q_kernel(
    const float* __restrict__ X, const float* __restrict__ W,
    const float* __restrict__ g, const float* __restrict__ b,
    const float* __restrict__ m, const float* __restrict__ v)
{
    gemm_bn_body(X, W, g, b, m, v, g_qbn);
}

__global__ void __launch_bounds__(256, 2) gemm_k_kernel(
    const float* __restrict__ X, const float* __restrict__ W,
    const float* __restrict__ g, const float* __restrict__ b,
    const float* __restrict__ m, const float* __restrict__ v)
{
    gemm_bn_body(X, W, g, b, m, v, g_kbn);
}

// ===========================================================================
// proj weight 3-way exact bf16 split (24 mantissa bits total)
// ===========================================================================
__global__ void wsplit_kernel(const float* __restrict__ w)
{
    int i = blockIdx.x * blockDim.x + threadIdx.x;
    if (i >= CH * CH) return;
    float v = w[i];
    __nv_bfloat16 b0 = __float2bfloat16(v);
    float r = v - __bfloat162float(b0);
    __nv_bfloat16 b1 = __float2bfloat16(r);
    r -= __bfloat162float(b1);
    __nv_bfloat16 b2 = __float2bfloat16(r);
    g_w0[i] = b0; g_w1[i] = b1; g_w2[i] = b2;
}

// ===========================================================================
// LIF on q,k + per-head sum-pool attention gate -> y as bf16 [n][c] row-major
// ===========================================================================
__global__ void lif_attn_kernel()
{
    int bh   = blockIdx.x;
    int b    = bh >> 3;
    int head = bh & 7;
    int hw   = threadIdx.x;
    if (hw >= HW) return;

    int cbase = head * DH;
    int base0 = b * CHW + cbase * HW + hw;

    float qs[4] = {0.f, 0.f, 0.f, 0.f};
    unsigned long long kb[4] = {0ull, 0ull, 0ull, 0ull};

    for (int d = 0; d < DH; d++) {
        int idx = base0 + d * HW;
        float vq = 0.f, vk = 0.f;
#pragma unroll
        for (int t = 0; t < 4; t++) {
            float xq = g_qbn[idx + t * BCHW];
            float xk = g_kbn[idx + t * BCHW];
            float hq = vq + (xq - vq) * 0.5f;
            float hk = vk + (xk - vk) * 0.5f;
            bool sq = (hq - 1.0f) >= 0.0f;
            bool sk = (hk - 1.0f) >= 0.0f;
            vq = sq ? 0.f : hq;
            vk = sk ? 0.f : hk;
            if (sq) qs[t] += 1.0f;
            if (sk) kb[t] |= (1ull << d);
        }
    }

    const __nv_bfloat16 ONE  = __float2bfloat16(1.0f);
    const __nv_bfloat16 ZERO = __float2bfloat16(0.0f);

    float va = 0.f;
#pragma unroll
    for (int t = 0; t < 4; t++) {
        float h = va + (qs[t] - va) * 0.5f;
        bool s  = (h - 0.5f) >= 0.0f;
        va = s ? 0.f : h;
        unsigned long long kbt = s ? kb[t] : 0ull;
        size_t ob = ((size_t)((t * BATCH + b) * HW + hw)) * CH + cbase;
        for (int d = 0; d < DH; d++)
            g_ybf[ob + d] = ((kbt >> d) & 1ull) ? ONE : ZERO;
    }
}

// ===========================================================================
// proj GEMM via mma.sync bf16 (baseline-family; valid at target sm_103):
// D[128m x 128n] = sum_p Wp[m][k] * Y[n][k],  p = 3 exact splits, Y binary.
// 8 warps as 4m x 2n; warp tile 32m x 64n = 2 x 8 m16n8k16 tiles.
// k-chunk 32, smem pitch 40 bf16 (80 B) -> conflict-free ldmatrix.
// ===========================================================================
#define KC      32
#define PITCH   40

__device__ __forceinline__ uint32_t smem_u32(const void* p) {
    uint32_t a;
    asm("{ .reg .u64 t; cvta.to.shared.u64 t, %1; cvt.u32.u64 %0, t; }"
        : "=r"(a) : "l"(p));
    return a;
}

__global__ void __launch_bounds__(256, 2) proj_mma_kernel(
    const float* __restrict__ gamma, const float* __restrict__ beta,
    const float* __restrict__ mean,  const float* __restrict__ var,
    const float* __restrict__ bias)
{
    __shared__ __nv_bfloat16 sA[3][128][PITCH];
    __shared__ __nv_bfloat16 sB[128][PITCH];
    __shared__ int colOff[128];

    const int tid  = threadIdx.x;
    const int wid  = tid >> 5;
    const int lane = tid & 31;
    const int mbase = blockIdx.y * 128;
    const int nbase = blockIdx.x * 128;

    if (tid < 128) {
        int n  = nbase + tid;
        int tb = n / HW;
        colOff[tid] = tb * CHW + (n - tb * HW);
    }

    const int wm = (wid & 3) * 32;       // warp m offset within tile
    const int wn = (wid >> 2) * 64;      // warp n offset within tile

    // ldmatrix source addresses (per-lane)
    //   A x4 tiles: (m0,k0)(m8,k0)(m0,k8)(m8,k8)
    const int a_r  = (lane & 7) + ((lane >> 3) & 1) * 8;   // row within m16
    const int a_kc = (lane >> 4) * 8;                      // k offset 0/8
    //   B x4 tiles: (n0,k0)(n0,k8)(n8,k0)(n8,k8)
    const int b_r  = (lane & 7) + (lane >> 4) * 8;         // row within n16
    const int b_kc = ((lane >> 3) & 1) * 8;

    const __nv_bfloat16* gw[3] = {
        g_w0 + (size_t)mbase * CH, g_w1 + (size_t)mbase * CH,
        g_w2 + (size_t)mbase * CH };
    const __nv_bfloat16* gy = g_ybf + (size_t)nbase * CH;

    float acc[2][8][4];
#pragma unroll
    for (int mt = 0; mt < 2; mt++)
#pragma unroll
        for (int nt = 0; nt < 8; nt++)
#pragma unroll
            for (int r = 0; r < 4; r++) acc[mt][nt][r] = 0.f;

    // loader: each pass covers 64 rows x 32 bf16 (4 x 16B per row);
    // 2 passes cover all 128 rows of each tile.
    const int l_row = tid >> 2;          // 0..63
    const int l_q   = (tid & 3) * 8;     // bf16 col offset (16 B chunks)

#pragma unroll 1
    for (int kc = 0; kc < CH / KC; kc++) {
        const int kbase = kc * KC;
        __syncthreads();   // previous chunk's smem reads complete
#pragma unroll
        for (int r2 = 0; r2 < 2; r2++) {
            const int row = l_row + r2 * 64;
#pragma unroll
            for (int p = 0; p < 3; p++)
                *reinterpret_cast<uint4*>(&sA[p][row][l_q]) =
                    *reinterpret_cast<const uint4*>(gw[p] + (size_t)row * CH + kbase + l_q);
            *reinterpret_cast<uint4*>(&sB[row][l_q]) =
                *reinterpret_cast<const uint4*>(gy + (size_t)row * CH + kbase + l_q);
        }
        __syncthreads();

#pragma unroll
        for (int p = 0; p < 3; p++) {
#pragma unroll
            for (int kk = 0; kk < 2; kk++) {
                const int k0 = kk * 16;
                uint32_t a[2][4];
#pragma unroll
                for (int mt = 0; mt < 2; mt++) {
                    uint32_t ad = smem_u32(&sA[p][wm + mt * 16 + a_r][k0 + a_kc]);
                    asm volatile(
                        "ldmatrix.sync.aligned.m8n8.x4.shared.b16 {%0,%1,%2,%3}, [%4];"
                        : "=r"(a[mt][0]), "=r"(a[mt][1]), "=r"(a[mt][2]), "=r"(a[mt][3])
                        : "r"(ad));
                }
#pragma unroll
                for (int nt2 = 0; nt2 < 4; nt2++) {
                    uint32_t b0, b1, b2, b3;
                    uint32_t bd = smem_u32(&sB[wn + nt2 * 16 + b_r][k0 + b_kc]);
                    asm volatile(
                        "ldmatrix.sync.aligned.m8n8.x4.shared.b16 {%0,%1,%2,%3}, [%4];"
                        : "=r"(b0), "=r"(b1), "=r"(b2), "=r"(b3) : "r"(bd));
#pragma unroll
                    for (int mt = 0; mt < 2; mt++) {
                        float* c = acc[mt][nt2 * 2];
                        asm volatile(
                            "mma.sync.aligned.m16n8k16.row.col.f32.bf16.bf16.f32 "
                            "{%0,%1,%2,%3}, {%4,%5,%6,%7}, {%8,%9}, {%0,%1,%2,%3};"
                            : "+f"(c[0]), "+f"(c[1]), "+f"(c[2]), "+f"(c[3])
                            : "r"(a[mt][0]), "r"(a[mt][1]), "r"(a[mt][2]), "r"(a[mt][3]),
                              "r"(b0), "r"(b1));
                        float* d = acc[mt][nt2 * 2 + 1];
                        asm volatile(
                            "mma.sync.aligned.m16n8k16.row.col.f32.bf16.bf16.f32 "
                            "{%0,%1,%2,%3}, {%4,%5,%6,%7}, {%8,%9}, {%0,%1,%2,%3};"
                            : "+f"(d[0]), "+f"(d[1]), "+f"(d[2]), "+f"(d[3])
                            : "r"(a[mt][0]), "r"(a[mt][1]), "r"(a[mt][2]), "r"(a[mt][3]),
                              "r"(b2), "r"(b3));
                    }
                }
            }
        }
    }

    // Epilogue: BN (+bias) then scatter store to g_zbn (NCHW layout)
#pragma unroll
    for (int mt = 0; mt < 2; mt++) {
        int oa = mbase + wm + mt * 16 + (lane >> 2);
        int ob = oa + 8;
        float inva = gamma[oa] / sqrtf(var[oa] + 1e-5f);
        float sha  = beta[oa] - mean[oa] * inva;
        float bva  = bias[oa];
        float invb = gamma[ob] / sqrtf(var[ob] + 1e-5f);
        float shb  = beta[ob] - mean[ob] * invb;
        float bvb  = bias[ob];
#pragma unroll
        for (int nt = 0; nt < 8; nt++) {
            int n  = wn + nt * 8 + (lane & 3) * 2;
            int c0 = colOff[n], c1 = colOff[n + 1];
            const float* c = acc[mt][nt];
            g_zbn[c0 + oa * HW] = (c[0] + bva) * inva + sha;
            g_zbn[c1 + oa * HW] = (c[1] + bva) * inva + sha;
            g_zbn[c0 + ob * HW] = (c[2] + bvb) * invb + shb;
            g_zbn[c1 + ob * HW] = (c[3] + bvb) * invb + shb;
        }
    }
}

// ===========================================================================
// Final LIF -> output spikes
// ===========================================================================
__global__ void lif_out_kernel(float* __restrict__ out)
{
    int idx = blockIdx.x * blockDim.x + threadIdx.x;
    if (idx >= BCHW) return;
    float v = 0.f;
#pragma unroll
    for (int t = 0; t < 4; t++) {
        float x = g_zbn[idx + t * BCHW];
        float h = v + (x - v) * 0.5f;
        bool s  = (h - 1.0f) >= 0.0f;
        v = s ? 0.f : h;
        out[idx + t * BCHW] = s ? 1.0f : 0.0f;
    }
}

// ===========================================================================
extern "C" void kernel_launch(void* const* d_in, const int* in_sizes, int n_in,
                              void* d_out, int out_size)
{
    const float* x          = (const float*)d_in[0];
    const float* q_w        = (const float*)d_in[1];
    const float* q_gamma    = (const float*)d_in[2];
    const float* q_beta     = (const float*)d_in[3];
    const float* q_mean     = (const float*)d_in[4];
    const float* q_var      = (const float*)d_in[5];
    const float* k_w        = (const float*)d_in[6];
    const float* k_gamma    = (const float*)d_in[7];
    const float* k_beta     = (const float*)d_in[8];
    const float* k_mean     = (const float*)d_in[9];
    const float* k_var      = (const float*)d_in[10];
    const float* proj_w     = (const float*)d_in[11];
    const float* proj_b     = (const float*)d_in[12];
    const float* proj_gamma = (const float*)d_in[13];
    const float* proj_beta  = (const float*)d_in[14];
    const float* proj_mean  = (const float*)d_in[15];
    const float* proj_var   = (const float*)d_in[16];

    dim3 ggrid(NTOT / 128, CH / 128);   // (196, 3)

    wsplit_kernel<<<(CH * CH + 255) / 256, 256>>>(proj_w);
    gemm_q_kernel<<<ggrid, 256>>>(x, q_w, q_gamma, q_beta, q_mean, q_var);
    gemm_k_kernel<<<ggrid, 256>>>(x, k_w, k_gamma, k_beta, k_mean, k_var);
    lif_attn_kernel<<<BATCH * HEADS, 224>>>();
    proj_mma_kernel<<<ggrid, 256>>>(proj_gamma, proj_beta,
                                    proj_mean, proj_var, proj_b);
    lif_out_kernel<<<(BCHW + 255) / 256, 256>>>((float*)d_out);
}

// round 8
// speedup vs baseline: 1.3837x; 1.3073x over previous
#include <cuda_runtime.h>
#include <cuda_bf16.h>
#include <cstdint>

// Problem constants
#define T_STEPS 4
#define BATCH   32
#define CH      384
#define HW      196
#define HEADS   8
#define DH      48
#define CHW     (CH*HW)          // 75264
#define BCHW    (BATCH*CHW)      // 2408448
#define TOTAL   (T_STEPS*BCHW)   // 9633792
#define NTOT    (T_STEPS*BATCH*HW) // 25088  (= 196 * 128 exactly)
#define NCHUNK  (CH/8)           // 48 k-chunks (fp32 SGEMM)

// Scratch (static device globals -- allocation-guard safe)
__device__ float g_qbn[TOTAL];
__device__ float g_kbn[TOTAL];
__device__ float g_zbn[TOTAL];
__device__ __nv_bfloat16 g_ybf[TOTAL];   // proj input, [n][c] row-major, exact 0/1
__device__ __nv_bfloat16 g_w0[CH*CH];    // proj_w 3-way exact bf16 split
__device__ __nv_bfloat16 g_w1[CH*CH];
__device__ __nv_bfloat16 g_w2[CH*CH];

// ===========================================================================
// Q/K SGEMM (R2 config: 128x128 tile, 8x8 microtile, 2 CTAs/SM, double-buffer)
// ===========================================================================
__device__ __forceinline__ void gemm_bn_body(
    const float* __restrict__ X, const float* __restrict__ W,
    const float* __restrict__ gamma, const float* __restrict__ beta,
    const float* __restrict__ mean,  const float* __restrict__ var,
    float* __restrict__ out)
{
    __shared__ float As[2][8][128];
    __shared__ float Bs[2][8][128];
    __shared__ int   colOff[128];

    const int tid   = threadIdx.x;
    const int mbase = blockIdx.y * 128;
    const int nbase = blockIdx.x * 128;

    if (tid < 128) {
        int n  = nbase + tid;
        int tb = n / HW;
        colOff[tid] = tb * CHW + (n - tb * HW);
    }
    __syncthreads();

    const int tx = tid & 15;
    const int ty = tid >> 4;

    const int a_row = tid >> 1;
    const int a_col = (tid & 1) * 4;
    const int b_k   = tid >> 5;
    const int b_n   = (tid & 31) * 4;

    const int bo0 = colOff[b_n + 0];
    const int bo1 = colOff[b_n + 1];
    const int bo2 = colOff[b_n + 2];
    const int bo3 = colOff[b_n + 3];

    const float* wptr = &W[(mbase + a_row) * CH + a_col];

    float acc[8][8];
#pragma unroll
    for (int i = 0; i < 8; i++)
#pragma unroll
        for (int j = 0; j < 8; j++) acc[i][j] = 0.f;

    {
        float4 av = *reinterpret_cast<const float4*>(wptr);
        const int krow = b_k * HW;
        As[0][a_col + 0][a_row] = av.x;
        As[0][a_col + 1][a_row] = av.y;
        As[0][a_col + 2][a_row] = av.z;
        As[0][a_col + 3][a_row] = av.w;
        *reinterpret_cast<float4*>(&Bs[0][b_k][b_n]) =
            make_float4(X[bo0 + krow], X[bo1 + krow], X[bo2 + krow], X[bo3 + krow]);
    }
    __syncthreads();

#define COMPUTE_STAGE(S)                                                        \
    _Pragma("unroll")                                                           \
    for (int k = 0; k < 8; k++) {                                               \
        float4 A0 = *reinterpret_cast<const float4*>(&As[S][k][ty * 4]);        \
        float4 A1 = *reinterpret_cast<const float4*>(&As[S][k][64 + ty * 4]);   \
        float4 B0 = *reinterpret_cast<const float4*>(&Bs[S][k][tx * 4]);        \
        float4 B1 = *reinterpret_cast<const float4*>(&Bs[S][k][64 + tx * 4]);   \
        float ar[8] = {A0.x, A0.y, A0.z, A0.w, A1.x, A1.y, A1.z, A1.w};         \
        float br[8] = {B0.x, B0.y, B0.z, B0.w, B1.x, B1.y, B1.z, B1.w};         \
        _Pragma("unroll")                                                       \
        for (int i = 0; i < 8; i++)                                             \
            _Pragma("unroll")                                                   \
            for (int j = 0; j < 8; j++)                                         \
                acc[i][j] = fmaf(ar[i], br[j], acc[i][j]);                      \
    }

#pragma unroll 1
    for (int it = 0; it < NCHUNK; it += 2) {
        {
            float4 av = *reinterpret_cast<const float4*>(wptr + (it + 1) * 8);
            const int krow = ((it + 1) * 8 + b_k) * HW;
            float x0 = X[bo0 + krow], x1 = X[bo1 + krow];
            float x2 = X[bo2 + krow], x3 = X[bo3 + krow];

            COMPUTE_STAGE(0)

            As[1][a_col + 0][a_row] = av.x;
            As[1][a_col + 1][a_row] = av.y;
            As[1][a_col + 2][a_row] = av.z;
            As[1][a_col + 3][a_row] = av.w;
            *reinterpret_cast<float4*>(&Bs[1][b_k][b_n]) = make_float4(x0, x1, x2, x3);
            __syncthreads();
        }
        if (it + 2 < NCHUNK) {
            float4 av = *reinterpret_cast<const float4*>(wptr + (it + 2) * 8);
            const int krow = ((it + 2) * 8 + b_k) * HW;
            float x0 = X[bo0 + krow], x1 = X[bo1 + krow];
            float x2 = X[bo2 + krow], x3 = X[bo3 + krow];

            COMPUTE_STAGE(1)

            As[0][a_col + 0][a_row] = av.x;
            As[0][a_col + 1][a_row] = av.y;
            As[0][a_col + 2][a_row] = av.z;
            As[0][a_col + 3][a_row] = av.w;
            *reinterpret_cast<float4*>(&Bs[0][b_k][b_n]) = make_float4(x0, x1, x2, x3);
            __syncthreads();
        } else {
            COMPUTE_STAGE(1)
        }
    }
#undef COMPUTE_STAGE

#pragma unroll
    for (int i = 0; i < 8; i++) {
        int m = (i < 4) ? (ty * 4 + i) : (64 + ty * 4 + (i - 4));
        int o = mbase + m;
        float inv = gamma[o] / sqrtf(var[o] + 1e-5f);
        float sh  = beta[o] - mean[o] * inv;
#pragma unroll
        for (int j = 0; j < 8; j++) {
            int n = (j < 4) ? (tx * 4 + j) : (64 + tx * 4 + (j - 4));
            out[colOff[n] + o * HW] = acc[i][j] * inv + sh;
        }
    }
}

__global__ void __launch_bounds__(256, 2) gemm_q_kernel(
    const float* __restrict__ X, const float* __restrict__ W,
    const float* __restrict__ g, const float* __restrict__ b,
    const float* __restrict__ m, const float* __restrict__ v)
{
    gemm_bn_body(X, W, g, b, m, v, g_qbn);
}

__global__ void __launch_bounds__(256, 2) gemm_k_kernel(
    const float* __restrict__ X, const float* __restrict__ W,
    const float* __restrict__ g, const float* __restrict__ b,
    const float* __restrict__ m, const float* __restrict__ v)
{
    gemm_bn_body(X, W, g, b, m, v, g_kbn);
}

// ===========================================================================
// proj weight 3-way exact bf16 split (24 mantissa bits total)
// ===========================================================================
__global__ void wsplit_kernel(const float* __restrict__ w)
{
    int i = blockIdx.x * blockDim.x + threadIdx.x;
    if (i >= CH * CH) return;
    float v = w[i];
    __nv_bfloat16 b0 = __float2bfloat16(v);
    float r = v - __bfloat162float(b0);
    __nv_bfloat16 b1 = __float2bfloat16(r);
    r -= __bfloat162float(b1);
    __nv_bfloat16 b2 = __float2bfloat16(r);
    g_w0[i] = b0; g_w1[i] = b1; g_w2[i] = b2;
}

// ===========================================================================
// LIF on q,k + per-head sum-pool attention gate -> y as bf16 [n][c] row-major.
// v2: 4-way d-split (block 224x4 = 28 warps), smem combine, packed uint4
// stores written cooperatively by all threads.
// ===========================================================================
__device__ __forceinline__ uint32_t pk2(uint32_t m) {
    // bits 0,1 -> packed bf16 pair (1.0f = 0x3F80)
    return ((m & 1u) ? 0x3F80u : 0u) | ((m & 2u) ? 0x3F800000u : 0u);
}

__global__ void __launch_bounds__(896) lif_attn_kernel()
{
    __shared__ float    s_qs[4][224][4];
    __shared__ uint32_t s_kb[4][224][4];
    __shared__ uint32_t s_m[224][4][2];   // gated masks: [hw][t][half]

    const int bh   = blockIdx.x;
    const int b    = bh >> 3;
    const int head = bh & 7;
    const int hw   = threadIdx.x;         // 0..223 (196 active)
    const int dg   = threadIdx.y;         // 0..3, 12 channels each
    const bool act = hw < HW;

    const int cb    = head * DH + dg * 12;
    const int base0 = b * CHW + cb * HW + hw;

    float    qs[4] = {0.f, 0.f, 0.f, 0.f};
    uint32_t kb[4] = {0u, 0u, 0u, 0u};

    if (act) {
#pragma unroll 1
        for (int d = 0; d < 12; d++) {
            int idx = base0 + d * HW;
            float vq = 0.f, vk = 0.f;
#pragma unroll
            for (int t = 0; t < 4; t++) {
                float xq = g_qbn[idx + t * BCHW];
                float xk = g_kbn[idx + t * BCHW];
                float hq = vq + (xq - vq) * 0.5f;
                float hk = vk + (xk - vk) * 0.5f;
                bool sq = (hq - 1.0f) >= 0.0f;
                bool sk = (hk - 1.0f) >= 0.0f;
                vq = sq ? 0.f : hq;
                vk = sk ? 0.f : hk;
                if (sq) qs[t] += 1.0f;
                if (sk) kb[t] |= (1u << d);
            }
        }
    }
#pragma unroll
    for (int t = 0; t < 4; t++) {
        s_qs[dg][hw][t] = qs[t];
        s_kb[dg][hw][t] = kb[t];
    }
    __syncthreads();

    if (dg == 0 && act) {
        float va = 0.f;
#pragma unroll
        for (int t = 0; t < 4; t++) {
            float q = qs[t] + s_qs[1][hw][t] + s_qs[2][hw][t] + s_qs[3][hw][t];
            uint32_t m0 = kb[t] | (s_kb[1][hw][t] << 12);
            uint32_t m1 = s_kb[2][hw][t] | (s_kb[3][hw][t] << 12);
            float h = va + (q - va) * 0.5f;
            bool s  = (h - 0.5f) >= 0.0f;    // v_th = 0.5
            va = s ? 0.f : h;
            s_m[hw][t][0] = s ? m0 : 0u;
            s_m[hw][t][1] = s ? m1 : 0u;
        }
    }
    __syncthreads();

    // Cooperative packed stores: 196 rows x 4 t x 6 uint4 (48 bf16/row)
    const int tidl = dg * 224 + hw;       // 0..895
#pragma unroll 1
    for (int l = tidl; l < HW * 4 * 6; l += 896) {
        int g  = l % 6;
        int r  = l / 6;          // 0..783
        int whw = r % HW;
        int t   = r / HW;
        uint32_t mask = s_m[whw][t][g >= 3 ? 1 : 0];
        uint32_t bits = mask >> ((g >= 3 ? g - 3 : g) * 8);
        uint4 v;
        v.x = pk2(bits);
        v.y = pk2(bits >> 2);
        v.z = pk2(bits >> 4);
        v.w = pk2(bits >> 6);
        size_t n = (size_t)((t * BATCH + b) * HW + whw);
        uint4* dst = reinterpret_cast<uint4*>(g_ybf + n * CH + head * DH);
        dst[g] = v;
    }
}

// ===========================================================================
// proj GEMM via mma.sync bf16 (baseline-family; valid at target sm_103):
// D[128m x 128n] = sum_p Wp[m][k] * Y[n][k],  p = 3 exact splits, Y binary.
// 8 warps as 4m x 2n; warp tile 32m x 64n = 2 x 8 m16n8k16 tiles.
// k-chunk 32, smem pitch 40 bf16 (80 B) -> conflict-free ldmatrix.
// ===========================================================================
#define KC      32
#define PITCH   40

__device__ __forceinline__ uint32_t smem_u32(const void* p) {
    uint32_t a;
    asm("{ .reg .u64 t; cvta.to.shared.u64 t, %1; cvt.u32.u64 %0, t; }"
        : "=r"(a) : "l"(p));
    return a;
}

__global__ void __launch_bounds__(256, 2) proj_mma_kernel(
    const float* __restrict__ gamma, const float* __restrict__ beta,
    const float* __restrict__ mean,  const float* __restrict__ var,
    const float* __restrict__ bias)
{
    __shared__ __nv_bfloat16 sA[3][128][PITCH];
    __shared__ __nv_bfloat16 sB[128][PITCH];
    __shared__ int colOff[128];

    const int tid  = threadIdx.x;
    const int wid  = tid >> 5;
    const int lane = tid & 31;
    const int mbase = blockIdx.y * 128;
    const int nbase = blockIdx.x * 128;

    if (tid < 128) {
        int n  = nbase + tid;
        int tb = n / HW;
        colOff[tid] = tb * CHW + (n - tb * HW);
    }

    const int wm = (wid & 3) * 32;
    const int wn = (wid >> 2) * 64;

    const int a_r  = (lane & 7) + ((lane >> 3) & 1) * 8;
    const int a_kc = (lane >> 4) * 8;
    const int b_r  = (lane & 7) + (lane >> 4) * 8;
    const int b_kc = ((lane >> 3) & 1) * 8;

    const __nv_bfloat16* gw[3] = {
        g_w0 + (size_t)mbase * CH, g_w1 + (size_t)mbase * CH,
        g_w2 + (size_t)mbase * CH };
    const __nv_bfloat16* gy = g_ybf + (size_t)nbase * CH;

    float acc[2][8][4];
#pragma unroll
    for (int mt = 0; mt < 2; mt++)
#pragma unroll
        for (int nt = 0; nt < 8; nt++)
#pragma unroll
            for (int r = 0; r < 4; r++) acc[mt][nt][r] = 0.f;

    const int l_row = tid >> 2;
    const int l_q   = (tid & 3) * 8;

#pragma unroll 1
    for (int kc = 0; kc < CH / KC; kc++) {
        const int kbase = kc * KC;
        __syncthreads();
#pragma unroll
        for (int r2 = 0; r2 < 2; r2++) {
            const int row = l_row + r2 * 64;
#pragma unroll
            for (int p = 0; p < 3; p++)
                *reinterpret_cast<uint4*>(&sA[p][row][l_q]) =
                    *reinterpret_cast<const uint4*>(gw[p] + (size_t)row * CH + kbase + l_q);
            *reinterpret_cast<uint4*>(&sB[row][l_q]) =
                *reinterpret_cast<const uint4*>(gy + (size_t)row * CH + kbase + l_q);
        }
        __syncthreads();

#pragma unroll
        for (int p = 0; p < 3; p++) {
#pragma unroll
            for (int kk = 0; kk < 2; kk++) {
                const int k0 = kk * 16;
                uint32_t a[2][4];
#pragma unroll
                for (int mt = 0; mt < 2; mt++) {
                    uint32_t ad = smem_u32(&sA[p][wm + mt * 16 + a_r][k0 + a_kc]);
                    asm volatile(
                        "ldmatrix.sync.aligned.m8n8.x4.shared.b16 {%0,%1,%2,%3}, [%4];"
                        : "=r"(a[mt][0]), "=r"(a[mt][1]), "=r"(a[mt][2]), "=r"(a[mt][3])
                        : "r"(ad));
                }
#pragma unroll
                for (int nt2 = 0; nt2 < 4; nt2++) {
                    uint32_t b0, b1, b2, b3;
                    uint32_t bd = smem_u32(&sB[wn + nt2 * 16 + b_r][k0 + b_kc]);
                    asm volatile(
                        "ldmatrix.sync.aligned.m8n8.x4.shared.b16 {%0,%1,%2,%3}, [%4];"
                        : "=r"(b0), "=r"(b1), "=r"(b2), "=r"(b3) : "r"(bd));
#pragma unroll
                    for (int mt = 0; mt < 2; mt++) {
                        float* c = acc[mt][nt2 * 2];
                        asm volatile(
                            "mma.sync.aligned.m16n8k16.row.col.f32.bf16.bf16.f32 "
                            "{%0,%1,%2,%3}, {%4,%5,%6,%7}, {%8,%9}, {%0,%1,%2,%3};"
                            : "+f"(c[0]), "+f"(c[1]), "+f"(c[2]), "+f"(c[3])
                            : "r"(a[mt][0]), "r"(a[mt][1]), "r"(a[mt][2]), "r"(a[mt][3]),
                              "r"(b0), "r"(b1));
                        float* d = acc[mt][nt2 * 2 + 1];
                        asm volatile(
                            "mma.sync.aligned.m16n8k16.row.col.f32.bf16.bf16.f32 "
                            "{%0,%1,%2,%3}, {%4,%5,%6,%7}, {%8,%9}, {%0,%1,%2,%3};"
                            : "+f"(d[0]), "+f"(d[1]), "+f"(d[2]), "+f"(d[3])
                            : "r"(a[mt][0]), "r"(a[mt][1]), "r"(a[mt][2]), "r"(a[mt][3]),
                              "r"(b2), "r"(b3));
                    }
                }
            }
        }
    }

    // Epilogue: BN (+bias) then scatter store to g_zbn (NCHW layout)
#pragma unroll
    for (int mt = 0; mt < 2; mt++) {
        int oa = mbase + wm + mt * 16 + (lane >> 2);
        int ob = oa + 8;
        float inva = gamma[oa] / sqrtf(var[oa] + 1e-5f);
        float sha  = beta[oa] - mean[oa] * inva;
        float bva  = bias[oa];
        float invb = gamma[ob] / sqrtf(var[ob] + 1e-5f);
        float shb  = beta[ob] - mean[ob] * invb;
        float bvb  = bias[ob];
#pragma unroll
        for (int nt = 0; nt < 8; nt++) {
            int n  = wn + nt * 8 + (lane & 3) * 2;
            int c0 = colOff[n], c1 = colOff[n + 1];
            const float* c = acc[mt][nt];
            g_zbn[c0 + oa * HW] = (c[0] + bva) * inva + sha;
            g_zbn[c1 + oa * HW] = (c[1] + bva) * inva + sha;
            g_zbn[c0 + ob * HW] = (c[2] + bvb) * invb + shb;
            g_zbn[c1 + ob * HW] = (c[3] + bvb) * invb + shb;
        }
    }
}

// ===========================================================================
// Final LIF -> output spikes
// ===========================================================================
__global__ void lif_out_kernel(float* __restrict__ out)
{
    int idx = blockIdx.x * blockDim.x + threadIdx.x;
    if (idx >= BCHW) return;
    float v = 0.f;
#pragma unroll
    for (int t = 0; t < 4; t++) {
        float x = g_zbn[idx + t * BCHW];
        float h = v + (x - v) * 0.5f;
        bool s  = (h - 1.0f) >= 0.0f;
        v = s ? 0.f : h;
        out[idx + t * BCHW] = s ? 1.0f : 0.0f;
    }
}

// ===========================================================================
extern "C" void kernel_launch(void* const* d_in, const int* in_sizes, int n_in,
                              void* d_out, int out_size)
{
    const float* x          = (const float*)d_in[0];
    const float* q_w        = (const float*)d_in[1];
    const float* q_gamma    = (const float*)d_in[2];
    const float* q_beta     = (const float*)d_in[3];
    const float* q_mean     = (const float*)d_in[4];
    const float* q_var      = (const float*)d_in[5];
    const float* k_w        = (const float*)d_in[6];
    const float* k_gamma    = (const float*)d_in[7];
    const float* k_beta     = (const float*)d_in[8];
    const float* k_mean     = (const float*)d_in[9];
    const float* k_var      = (const float*)d_in[10];
    const float* proj_w     = (const float*)d_in[11];
    const float* proj_b     = (const float*)d_in[12];
    const float* proj_gamma = (const float*)d_in[13];
    const float* proj_beta  = (const float*)d_in[14];
    const float* proj_mean  = (const float*)d_in[15];
    const float* proj_var   = (const float*)d_in[16];

    dim3 ggrid(NTOT / 128, CH / 128);   // (196, 3)

    wsplit_kernel<<<(CH * CH + 255) / 256, 256>>>(proj_w);
    gemm_q_kernel<<<ggrid, 256>>>(x, q_w, q_gamma, q_beta, q_mean, q_var);
    gemm_k_kernel<<<ggrid, 256>>>(x, k_w, k_gamma, k_beta, k_mean, k_var);
    lif_attn_kernel<<<BATCH * HEADS, dim3(224, 4)>>>();
    proj_mma_kernel<<<ggrid, 256>>>(proj_gamma, proj_beta,
                                    proj_mean, proj_var, proj_b);
    lif_out_kernel<<<(BCHW + 255) / 256, 256>>>((float*)d_out);
}

// round 9
// speedup vs baseline: 1.4564x; 1.0525x over previous
#include <cuda_runtime.h>
#include <cuda_bf16.h>
#include <cstdint>

// Problem constants
#define T_STEPS 4
#define BATCH   32
#define CH      384
#define HW      196
#define HEADS   8
#define DH      48
#define CHW     (CH*HW)          // 75264
#define BCHW    (BATCH*CHW)      // 2408448
#define TOTAL   (T_STEPS*BCHW)   // 9633792
#define NTOT    (T_STEPS*BATCH*HW) // 25088  (= 196 * 128 exactly)

// Scratch (static device globals -- allocation-guard safe)
__device__ float g_qbn[TOTAL];
__device__ float g_kbn[TOTAL];
__device__ float g_zbn[TOTAL];
__device__ __nv_bfloat16 g_ybf[TOTAL];   // proj input, [n][c] row-major, exact 0/1
__device__ __nv_bfloat16 g_w0[CH*CH];    // proj_w 3-way exact bf16 split
__device__ __nv_bfloat16 g_w1[CH*CH];
__device__ __nv_bfloat16 g_w2[CH*CH];
__device__ __nv_bfloat16 g_qw0[CH*CH];   // q_w split
__device__ __nv_bfloat16 g_qw1[CH*CH];
__device__ __nv_bfloat16 g_qw2[CH*CH];
__device__ __nv_bfloat16 g_kw0[CH*CH];   // k_w split
__device__ __nv_bfloat16 g_kw1[CH*CH];
__device__ __nv_bfloat16 g_kw2[CH*CH];

__device__ __forceinline__ uint32_t smem_u32(const void* p) {
    uint32_t a;
    asm("{ .reg .u64 t; cvta.to.shared.u64 t, %1; cvt.u32.u64 %0, t; }"
        : "=r"(a) : "l"(p));
    return a;
}

#define MMA16816(CP, A0, A1, A2, A3, B0, B1)                                    \
    asm volatile(                                                               \
        "mma.sync.aligned.m16n8k16.row.col.f32.bf16.bf16.f32 "                  \
        "{%0,%1,%2,%3}, {%4,%5,%6,%7}, {%8,%9}, {%0,%1,%2,%3};"                 \
        : "+f"((CP)[0]), "+f"((CP)[1]), "+f"((CP)[2]), "+f"((CP)[3])            \
        : "r"(A0), "r"(A1), "r"(A2), "r"(A3), "r"(B0), "r"(B1))

#define LDMX4(R0, R1, R2, R3, AD)                                               \
    asm volatile("ldmatrix.sync.aligned.m8n8.x4.shared.b16 {%0,%1,%2,%3}, [%4];"\
        : "=r"(R0), "=r"(R1), "=r"(R2), "=r"(R3) : "r"(AD))

// ===========================================================================
// weight 3-way exact bf16 split (24 mantissa bits total)
// ===========================================================================
__global__ void wsplit_kernel(const float* __restrict__ w,
                              __nv_bfloat16* __restrict__ o0,
                              __nv_bfloat16* __restrict__ o1,
                              __nv_bfloat16* __restrict__ o2)
{
    int i = blockIdx.x * blockDim.x + threadIdx.x;
    if (i >= CH * CH) return;
    float v = w[i];
    __nv_bfloat16 b0 = __float2bfloat16(v);
    float r = v - __bfloat162float(b0);
    __nv_bfloat16 b1 = __float2bfloat16(r);
    r -= __bfloat162float(b1);
    __nv_bfloat16 b2 = __float2bfloat16(r);
    o0[i] = b0; o1[i] = b1; o2[i] = b2;
}

// ===========================================================================
// Q/K GEMM via 6-term split-bf16 mma.sync:
//   BN(W @ X):  W = w0+w1+w2 (bf16, exact), X split inline to x0+x1+x2.
//   D = sum over (i,j), i+j<=2 of wi @ xj   (error ~ fp32 reorder noise)
// CTA tile 128m x 128n, KC=32, 8 warps (4m x 2n), warp tile 32x64.
// smem: 3 A-planes + 3 B-planes, pitch 40 bf16 (conflict-free ldmatrix).
// ===========================================================================
#define QKC    32
#define QP     40
#define QK_SMEM (6*128*QP*2 + 512)

__global__ void __launch_bounds__(256, 2) qk_mma_kernel(
    const float* __restrict__ X,
    const __nv_bfloat16* __restrict__ w0,
    const __nv_bfloat16* __restrict__ w1,
    const __nv_bfloat16* __restrict__ w2,
    const float* __restrict__ gamma, const float* __restrict__ beta,
    const float* __restrict__ mean,  const float* __restrict__ var,
    float* __restrict__ out)
{
    extern __shared__ char dsm[];
    __nv_bfloat16* sAb = reinterpret_cast<__nv_bfloat16*>(dsm);           // [3][128][QP]
    __nv_bfloat16* sBb = sAb + 3 * 128 * QP;                              // [3][128][QP]
    int* colOff = reinterpret_cast<int*>(sBb + 3 * 128 * QP);

#define SA(P, R, C) sAb[((P) * 128 + (R)) * QP + (C)]
#define SB(P, R, C) sBb[((P) * 128 + (R)) * QP + (C)]

    const int tid  = threadIdx.x;
    const int wid  = tid >> 5;
    const int lane = tid & 31;
    const int mbase = blockIdx.y * 128;
    const int nbase = blockIdx.x * 128;

    if (tid < 128) {
        int n  = nbase + tid;
        int tb = n / HW;
        colOff[tid] = tb * CHW + (n - tb * HW);
    }
    __syncthreads();

    // loader mapping: each thread owns one row (A: m-row, B: n-row), 16 k
    const int ln  = tid >> 1;            // 0..127
    const int lkq = (tid & 1) * 16;      // 0 or 16
    const int bo  = colOff[ln];

    const __nv_bfloat16* gw[3] = {
        w0 + (size_t)(mbase + ln) * CH + lkq,
        w1 + (size_t)(mbase + ln) * CH + lkq,
        w2 + (size_t)(mbase + ln) * CH + lkq };

    const int wm = (wid & 3) * 32;
    const int wn = (wid >> 2) * 64;

    const int a_r  = (lane & 7) + ((lane >> 3) & 1) * 8;
    const int a_kc = (lane >> 4) * 8;
    const int b_r  = (lane & 7) + (lane >> 4) * 8;
    const int b_kc = ((lane >> 3) & 1) * 8;

    float acc[2][8][4];
#pragma unroll
    for (int mt = 0; mt < 2; mt++)
#pragma unroll
        for (int nt = 0; nt < 8; nt++)
#pragma unroll
            for (int r = 0; r < 4; r++) acc[mt][nt][r] = 0.f;

#pragma unroll 1
    for (int kc = 0; kc < CH / QKC; kc++) {
        const int kbase = kc * QKC;
        __syncthreads();   // prior chunk's smem reads complete

        // A: 3 weight planes, bf16, 16 per thread per plane (2 x uint4)
#pragma unroll
        for (int p = 0; p < 3; p++) {
            const uint4* s = reinterpret_cast<const uint4*>(gw[p] + kbase);
            *reinterpret_cast<uint4*>(&SA(p, ln, lkq))     = s[0];
            *reinterpret_cast<uint4*>(&SA(p, ln, lkq + 8)) = s[1];
        }
        // B: X fp32 gather -> inline 3-way exact bf16 split -> 3 planes
        {
            __nv_bfloat16 xb0[16], xb1[16], xb2[16];
#pragma unroll
            for (int i = 0; i < 16; i++) {
                float v = X[bo + (kbase + lkq + i) * HW];
                __nv_bfloat16 b0 = __float2bfloat16(v);
                float r = v - __bfloat162float(b0);
                __nv_bfloat16 b1 = __float2bfloat16(r);
                r -= __bfloat162float(b1);
                xb0[i] = b0; xb1[i] = b1; xb2[i] = __float2bfloat16(r);
            }
            const uint4* u0 = reinterpret_cast<const uint4*>(xb0);
            const uint4* u1 = reinterpret_cast<const uint4*>(xb1);
            const uint4* u2 = reinterpret_cast<const uint4*>(xb2);
            *reinterpret_cast<uint4*>(&SB(0, ln, lkq))     = u0[0];
            *reinterpret_cast<uint4*>(&SB(0, ln, lkq + 8)) = u0[1];
            *reinterpret_cast<uint4*>(&SB(1, ln, lkq))     = u1[0];
            *reinterpret_cast<uint4*>(&SB(1, ln, lkq + 8)) = u1[1];
            *reinterpret_cast<uint4*>(&SB(2, ln, lkq))     = u2[0];
            *reinterpret_cast<uint4*>(&SB(2, ln, lkq + 8)) = u2[1];
        }
        __syncthreads();

#pragma unroll
        for (int kk = 0; kk < 2; kk++) {
            const int k0 = kk * 16;
            uint32_t a[3][2][4];
#pragma unroll
            for (int p = 0; p < 3; p++)
#pragma unroll
                for (int mt = 0; mt < 2; mt++) {
                    uint32_t ad = smem_u32(&SA(p, wm + mt * 16 + a_r, k0 + a_kc));
                    LDMX4(a[p][mt][0], a[p][mt][1], a[p][mt][2], a[p][mt][3], ad);
                }
#pragma unroll
            for (int nt2 = 0; nt2 < 4; nt2++) {
                uint32_t b[3][4];
#pragma unroll
                for (int p = 0; p < 3; p++) {
                    uint32_t bd = smem_u32(&SB(p, wn + nt2 * 16 + b_r, k0 + b_kc));
                    LDMX4(b[p][0], b[p][1], b[p][2], b[p][3], bd);
                }
                // 6 exact product terms: (i,j) with i+j<=2
#define QK_PAIR(I, J)                                                           \
                _Pragma("unroll")                                               \
                for (int mt = 0; mt < 2; mt++) {                                \
                    MMA16816(acc[mt][nt2 * 2],                                  \
                             a[I][mt][0], a[I][mt][1], a[I][mt][2], a[I][mt][3],\
                             b[J][0], b[J][1]);                                 \
                    MMA16816(acc[mt][nt2 * 2 + 1],                              \
                             a[I][mt][0], a[I][mt][1], a[I][mt][2], a[I][mt][3],\
                             b[J][2], b[J][3]);                                 \
                }
                QK_PAIR(0, 0)
                QK_PAIR(0, 1)
                QK_PAIR(1, 0)
                QK_PAIR(1, 1)
                QK_PAIR(2, 0)
                QK_PAIR(0, 2)
#undef QK_PAIR
            }
        }
    }

    // Epilogue: BN then scatter store (NCHW layout)
#pragma unroll
    for (int mt = 0; mt < 2; mt++) {
        int oa = mbase + wm + mt * 16 + (lane >> 2);
        int ob = oa + 8;
        float inva = gamma[oa] / sqrtf(var[oa] + 1e-5f);
        float sha  = beta[oa] - mean[oa] * inva;
        float invb = gamma[ob] / sqrtf(var[ob] + 1e-5f);
        float shb  = beta[ob] - mean[ob] * invb;
#pragma unroll
        for (int nt = 0; nt < 8; nt++) {
            int n  = wn + nt * 8 + (lane & 3) * 2;
            int c0 = colOff[n], c1 = colOff[n + 1];
            const float* c = acc[mt][nt];
            out[c0 + oa * HW] = c[0] * inva + sha;
            out[c1 + oa * HW] = c[1] * inva + sha;
            out[c0 + ob * HW] = c[2] * invb + shb;
            out[c1 + ob * HW] = c[3] * invb + shb;
        }
    }
#undef SA
#undef SB
}

// ===========================================================================
// LIF on q,k + per-head sum-pool attention gate -> y as bf16 [n][c] row-major.
// 4-way d-split (block 224x4 = 28 warps), smem combine, packed uint4 stores.
// ===========================================================================
__device__ __forceinline__ uint32_t pk2(uint32_t m) {
    return ((m & 1u) ? 0x3F80u : 0u) | ((m & 2u) ? 0x3F800000u : 0u);
}

__global__ void __launch_bounds__(896) lif_attn_kernel()
{
    __shared__ float    s_qs[4][224][4];
    __shared__ uint32_t s_kb[4][224][4];
    __shared__ uint32_t s_m[224][4][2];

    const int bh   = blockIdx.x;
    const int b    = bh >> 3;
    const int head = bh & 7;
    const int hw   = threadIdx.x;
    const int dg   = threadIdx.y;
    const bool act = hw < HW;

    const int cb    = head * DH + dg * 12;
    const int base0 = b * CHW + cb * HW + hw;

    float    qs[4] = {0.f, 0.f, 0.f, 0.f};
    uint32_t kb[4] = {0u, 0u, 0u, 0u};

    if (act) {
#pragma unroll 1
        for (int d = 0; d < 12; d++) {
            int idx = base0 + d * HW;
            float vq = 0.f, vk = 0.f;
#pragma unroll
            for (int t = 0; t < 4; t++) {
                float xq = g_qbn[idx + t * BCHW];
                float xk = g_kbn[idx + t * BCHW];
                float hq = vq + (xq - vq) * 0.5f;
                float hk = vk + (xk - vk) * 0.5f;
                bool sq = (hq - 1.0f) >= 0.0f;
                bool sk = (hk - 1.0f) >= 0.0f;
                vq = sq ? 0.f : hq;
                vk = sk ? 0.f : hk;
                if (sq) qs[t] += 1.0f;
                if (sk) kb[t] |= (1u << d);
            }
        }
    }
#pragma unroll
    for (int t = 0; t < 4; t++) {
        s_qs[dg][hw][t] = qs[t];
        s_kb[dg][hw][t] = kb[t];
    }
    __syncthreads();

    if (dg == 0 && act) {
        float va = 0.f;
#pragma unroll
        for (int t = 0; t < 4; t++) {
            float q = qs[t] + s_qs[1][hw][t] + s_qs[2][hw][t] + s_qs[3][hw][t];
            uint32_t m0 = kb[t] | (s_kb[1][hw][t] << 12);
            uint32_t m1 = s_kb[2][hw][t] | (s_kb[3][hw][t] << 12);
            float h = va + (q - va) * 0.5f;
            bool s  = (h - 0.5f) >= 0.0f;
            va = s ? 0.f : h;
            s_m[hw][t][0] = s ? m0 : 0u;
            s_m[hw][t][1] = s ? m1 : 0u;
        }
    }
    __syncthreads();

    const int tidl = dg * 224 + hw;
#pragma unroll 1
    for (int l = tidl; l < HW * 4 * 6; l += 896) {
        int g  = l % 6;
        int r  = l / 6;
        int whw = r % HW;
        int t   = r / HW;
        uint32_t mask = s_m[whw][t][g >= 3 ? 1 : 0];
        uint32_t bits = mask >> ((g >= 3 ? g - 3 : g) * 8);
        uint4 v;
        v.x = pk2(bits);
        v.y = pk2(bits >> 2);
        v.z = pk2(bits >> 4);
        v.w = pk2(bits >> 6);
        size_t n = (size_t)((t * BATCH + b) * HW + whw);
        uint4* dst = reinterpret_cast<uint4*>(g_ybf + n * CH + head * DH);
        dst[g] = v;
    }
}

// ===========================================================================
// proj GEMM via mma.sync bf16 (3 exact splits x binary Y)  -- proven R6/R7
// ===========================================================================
#define KC      32
#define PITCH   40

__global__ void __launch_bounds__(256, 2) proj_mma_kernel(
    const float* __restrict__ gamma, const float* __restrict__ beta,
    const float* __restrict__ mean,  const float* __restrict__ var,
    const float* __restrict__ bias)
{
    __shared__ __nv_bfloat16 sA[3][128][PITCH];
    __shared__ __nv_bfloat16 sB[128][PITCH];
    __shared__ int colOff[128];

    const int tid  = threadIdx.x;
    const int wid  = tid >> 5;
    const int lane = tid & 31;
    const int mbase = blockIdx.y * 128;
    const int nbase = blockIdx.x * 128;

    if (tid < 128) {
        int n  = nbase + tid;
        int tb = n / HW;
        colOff[tid] = tb * CHW + (n - tb * HW);
    }

    const int wm = (wid & 3) * 32;
    const int wn = (wid >> 2) * 64;

    const int a_r  = (lane & 7) + ((lane >> 3) & 1) * 8;
    const int a_kc = (lane >> 4) * 8;
    const int b_r  = (lane & 7) + (lane >> 4) * 8;
    const int b_kc = ((lane >> 3) & 1) * 8;

    const __nv_bfloat16* gw[3] = {
        g_w0 + (size_t)mbase * CH, g_w1 + (size_t)mbase * CH,
        g_w2 + (size_t)mbase * CH };
    const __nv_bfloat16* gy = g_ybf + (size_t)nbase * CH;

    float acc[2][8][4];
#pragma unroll
    for (int mt = 0; mt < 2; mt++)
#pragma unroll
        for (int nt = 0; nt < 8; nt++)
#pragma unroll
            for (int r = 0; r < 4; r++) acc[mt][nt][r] = 0.f;

    const int l_row = tid >> 2;
    const int l_q   = (tid & 3) * 8;

#pragma unroll 1
    for (int kc = 0; kc < CH / KC; kc++) {
        const int kbase = kc * KC;
        __syncthreads();
#pragma unroll
        for (int r2 = 0; r2 < 2; r2++) {
            const int row = l_row + r2 * 64;
#pragma unroll
            for (int p = 0; p < 3; p++)
                *reinterpret_cast<uint4*>(&sA[p][row][l_q]) =
                    *reinterpret_cast<const uint4*>(gw[p] + (size_t)row * CH + kbase + l_q);
            *reinterpret_cast<uint4*>(&sB[row][l_q]) =
                *reinterpret_cast<const uint4*>(gy + (size_t)row * CH + kbase + l_q);
        }
        __syncthreads();

#pragma unroll
        for (int p = 0; p < 3; p++) {
#pragma unroll
            for (int kk = 0; kk < 2; kk++) {
                const int k0 = kk * 16;
                uint32_t a[2][4];
#pragma unroll
                for (int mt = 0; mt < 2; mt++) {
                    uint32_t ad = smem_u32(&sA[p][wm + mt * 16 + a_r][k0 + a_kc]);
                    LDMX4(a[mt][0], a[mt][1], a[mt][2], a[mt][3], ad);
                }
#pragma unroll
                for (int nt2 = 0; nt2 < 4; nt2++) {
                    uint32_t b0, b1, b2, b3;
                    uint32_t bd = smem_u32(&sB[wn + nt2 * 16 + b_r][k0 + b_kc]);
                    LDMX4(b0, b1, b2, b3, bd);
#pragma unroll
                    for (int mt = 0; mt < 2; mt++) {
                        MMA16816(acc[mt][nt2 * 2],
                                 a[mt][0], a[mt][1], a[mt][2], a[mt][3], b0, b1);
                        MMA16816(acc[mt][nt2 * 2 + 1],
                                 a[mt][0], a[mt][1], a[mt][2], a[mt][3], b2, b3);
                    }
                }
            }
        }
    }

#pragma unroll
    for (int mt = 0; mt < 2; mt++) {
        int oa = mbase + wm + mt * 16 + (lane >> 2);
        int ob = oa + 8;
        float inva = gamma[oa] / sqrtf(var[oa] + 1e-5f);
        float sha  = beta[oa] - mean[oa] * inva;
        float bva  = bias[oa];
        float invb = gamma[ob] / sqrtf(var[ob] + 1e-5f);
        float shb  = beta[ob] - mean[ob] * invb;
        float bvb  = bias[ob];
#pragma unroll
        for (int nt = 0; nt < 8; nt++) {
            int n  = wn + nt * 8 + (lane & 3) * 2;
            int c0 = colOff[n], c1 = colOff[n + 1];
            const float* c = acc[mt][nt];
            g_zbn[c0 + oa * HW] = (c[0] + bva) * inva + sha;
            g_zbn[c1 + oa * HW] = (c[1] + bva) * inva + sha;
            g_zbn[c0 + ob * HW] = (c[2] + bvb) * invb + shb;
            g_zbn[c1 + ob * HW] = (c[3] + bvb) * invb + shb;
        }
    }
}

// ===========================================================================
// Final LIF -> output spikes
// ===========================================================================
__global__ void lif_out_kernel(float* __restrict__ out)
{
    int idx = blockIdx.x * blockDim.x + threadIdx.x;
    if (idx >= BCHW) return;
    float v = 0.f;
#pragma unroll
    for (int t = 0; t < 4; t++) {
        float x = g_zbn[idx + t * BCHW];
        float h = v + (x - v) * 0.5f;
        bool s  = (h - 1.0f) >= 0.0f;
        v = s ? 0.f : h;
        out[idx + t * BCHW] = s ? 1.0f : 0.0f;
    }
}

// ===========================================================================
extern "C" void kernel_launch(void* const* d_in, const int* in_sizes, int n_in,
                              void* d_out, int out_size)
{
    const float* x          = (const float*)d_in[0];
    const float* q_w        = (const float*)d_in[1];
    const float* q_gamma    = (const float*)d_in[2];
    const float* q_beta     = (const float*)d_in[3];
    const float* q_mean     = (const float*)d_in[4];
    const float* q_var      = (const float*)d_in[5];
    const float* k_w        = (const float*)d_in[6];
    const float* k_gamma    = (const float*)d_in[7];
    const float* k_beta     = (const float*)d_in[8];
    const float* k_mean     = (const float*)d_in[9];
    const float* k_var      = (const float*)d_in[10];
    const float* proj_w     = (const float*)d_in[11];
    const float* proj_b     = (const float*)d_in[12];
    const float* proj_gamma = (const float*)d_in[13];
    const float* proj_beta  = (const float*)d_in[14];
    const float* proj_mean  = (const float*)d_in[15];
    const float* proj_var   = (const float*)d_in[16];

    static bool attr_set = false;
    if (!attr_set) {
        cudaFuncSetAttribute(qk_mma_kernel,
                             cudaFuncAttributeMaxDynamicSharedMemorySize, QK_SMEM);
        attr_set = true;
    }

    // resolve device-global symbol addresses (host side, graph-safe)
    __nv_bfloat16 *qw0, *qw1, *qw2, *kw0, *kw1, *kw2, *pw0, *pw1, *pw2;
    cudaGetSymbolAddress((void**)&qw0, g_qw0);
    cudaGetSymbolAddress((void**)&qw1, g_qw1);
    cudaGetSymbolAddress((void**)&qw2, g_qw2);
    cudaGetSymbolAddress((void**)&kw0, g_kw0);
    cudaGetSymbolAddress((void**)&kw1, g_kw1);
    cudaGetSymbolAddress((void**)&kw2, g_kw2);
    cudaGetSymbolAddress((void**)&pw0, g_w0);
    cudaGetSymbolAddress((void**)&pw1, g_w1);
    cudaGetSymbolAddress((void**)&pw2, g_w2);
    float* qbn; float* kbn;
    cudaGetSymbolAddress((void**)&qbn, g_qbn);
    cudaGetSymbolAddress((void**)&kbn, g_kbn);

    dim3 ggrid(NTOT / 128, CH / 128);   // (196, 3)
    int wthreads = (CH * CH + 255) / 256;

    wsplit_kernel<<<wthreads, 256>>>(q_w, qw0, qw1, qw2);
    wsplit_kernel<<<wthreads, 256>>>(k_w, kw0, kw1, kw2);
    wsplit_kernel<<<wthreads, 256>>>(proj_w, pw0, pw1, pw2);
    qk_mma_kernel<<<ggrid, 256, QK_SMEM>>>(x, qw0, qw1, qw2,
                                           q_gamma, q_beta, q_mean, q_var, qbn);
    qk_mma_kernel<<<ggrid, 256, QK_SMEM>>>(x, kw0, kw1, kw2,
                                           k_gamma, k_beta, k_mean, k_var, kbn);
    lif_attn_kernel<<<BATCH * HEADS, dim3(224, 4)>>>();
    proj_mma_kernel<<<ggrid, 256>>>(proj_gamma, proj_beta,
                                    proj_mean, proj_var, proj_b);
    lif_out_kernel<<<(BCHW + 255) / 256, 256>>>((float*)d_out);
}